// round 1
// baseline (speedup 1.0000x reference)
#include <cuda_runtime.h>
#include <math.h>

#define NN 50000
#define EE 800000
#define HH 256
#define H2 512
#define EDD 13

// ---- device scratch (allocation-free rule: __device__ globals) ----
__device__ float g_P1[(size_t)NN * H2];     // h @ W_e1[0:256]     (100 MB)
__device__ float g_P2[(size_t)NN * H2];     // h @ W_e1[256:512]   (100 MB)
__device__ float g_agg[(size_t)NN * HH];    // segment_sum(m*att)
__device__ float g_cagg[(size_t)NN * 3];    // segment_sum(diff*coord_w)
__device__ float g_uagg[(size_t)NN * HH];   // segment_sum(silu(d*Wf1+bf1))
__device__ float g_deg[NN];                 // per-row edge count
__device__ float g_nln[(size_t)NN * H2];    // node LN intermediate

__device__ __forceinline__ float silu_f(float x) { return x / (1.f + __expf(-x)); }
__device__ __forceinline__ float sigm_f(float x) { return 1.f / (1.f + __expf(-x)); }

// ---------------------------------------------------------------- zero scratch
__global__ void k_zero() {
    size_t i = (size_t)blockIdx.x * 256 + threadIdx.x;   // grid = NN*HH/256
    g_agg[i] = 0.f;
    g_uagg[i] = 0.f;
    if (i < (size_t)NN * 3) g_cagg[i] = 0.f;
    if (i < NN) g_deg[i] = 0.f;
}

// ---------------------------------------------------------------- P1/P2 = h @ W_e1 halves
// grid (ceil(N/32), 4): y&1 -> column half (0..255 / 256..511), y>>1 -> P1/P2 (row half of W_e1)
__global__ __launch_bounds__(256) void k_pre(const float* __restrict__ h,
                                             const float* __restrict__ We1) {
    __shared__ float hs[32 * HH];
    int tid = threadIdx.x;
    int nb = blockIdx.x * 32;
    for (int i = tid; i < 32 * HH / 4; i += 256) {
        int r = (i * 4) >> 8, c = (i * 4) & 255;
        int node = nb + r;
        float4 v = make_float4(0.f, 0.f, 0.f, 0.f);
        if (node < NN) v = *(const float4*)&h[(size_t)node * HH + c];
        *(float4*)&hs[r * HH + c] = v;
    }
    __syncthreads();
    int isP2 = blockIdx.y >> 1;
    int cb = (blockIdx.y & 1) * 256;
    const float* W = We1 + (size_t)isP2 * HH * H2;
    float* outp = isP2 ? g_P2 : g_P1;
    int tx = tid & 63, ty = tid >> 6;
    int n0 = cb + tx * 4, e0 = ty * 8;
    float acc[8][4] = {};
#pragma unroll 4
    for (int k = 0; k < HH; k++) {
        float4 w = *(const float4*)&W[(size_t)k * H2 + n0];
#pragma unroll
        for (int i = 0; i < 8; i++) {
            float a = hs[(e0 + i) * HH + k];
            acc[i][0] += a * w.x; acc[i][1] += a * w.y;
            acc[i][2] += a * w.z; acc[i][3] += a * w.w;
        }
    }
#pragma unroll
    for (int i = 0; i < 8; i++) {
        int node = nb + e0 + i;
        if (node < NN)
            *(float4*)&outp[(size_t)node * H2 + n0] =
                make_float4(acc[i][0], acc[i][1], acc[i][2], acc[i][3]);
    }
}

// ---------------------------------------------------------------- fused edge kernel
// 32 edges / block. t=silu -> LN -> m=silu(GEMM) -> att -> c-gate -> scatter atomics.
static const int SME_FLOATS = 32 * H2 + 32 * HH + EDD * H2 + 32 * EDD + 32 + 96 + 32 + 32 + 64;

__global__ __launch_bounds__(256) void k_edge(
    const float* __restrict__ pos, const int* __restrict__ ei, const float* __restrict__ ea,
    const float* __restrict__ We1, const float* __restrict__ be1,
    const float* __restrict__ ge, const float* __restrict__ beln,
    const float* __restrict__ We2, const float* __restrict__ be2,
    const float* __restrict__ Wc1, const float* __restrict__ bc1, const float* __restrict__ Wc2,
    const float* __restrict__ Wa, const float* __restrict__ ba) {
    extern __shared__ float sm[];
    float* t_s = sm;                      // 32*512
    float* m_s = t_s + 32 * H2;           // 32*256
    float* w1e = m_s + 32 * HH;           // 13*512
    float* ea_s = w1e + EDD * H2;         // 32*13
    float* dist_s = ea_s + 32 * EDD;      // 32
    float* diff_s = dist_s + 32;          // 96
    float* att_s = diff_s + 96;           // 32
    float* cw_s = att_s + 32;             // 32
    int* row_s = (int*)(cw_s + 32);       // 32
    int* col_s = row_s + 32;              // 32

    int tid = threadIdx.x;
    int e0g = blockIdx.x * 32;

    for (int i = tid; i < EDD * H2 / 4; i += 256)
        *(float4*)&w1e[i * 4] = *(const float4*)&We1[(size_t)513 * H2 + i * 4];
    for (int i = tid; i < 32 * EDD; i += 256)
        ea_s[i] = ea[(size_t)e0g * EDD + i];
    if (tid < 32) {
        int e = e0g + tid;
        int r = ei[e], c = ei[EE + e];
        row_s[tid] = r; col_s[tid] = c;
        float dx = pos[r * 3 + 0] - pos[c * 3 + 0];
        float dy = pos[r * 3 + 1] - pos[c * 3 + 1];
        float dz = pos[r * 3 + 2] - pos[c * 3 + 2];
        diff_s[tid * 3 + 0] = dx; diff_s[tid * 3 + 1] = dy; diff_s[tid * 3 + 2] = dz;
        dist_s[tid] = fmaxf(sqrtf(dx * dx + dy * dy + dz * dz), 1e-5f);
        att_s[tid] = 0.f; cw_s[tid] = 0.f;
    }
    __syncthreads();

    // Stage 1: t_s = silu(P1[row] + P2[col] + dist*w_d + ea@W1e + b_e1)
    for (int idx = tid; idx < 32 * (H2 / 4); idx += 256) {
        int e = idx >> 7;
        int j = (idx & 127) * 4;
        int r = row_s[e], c = col_s[e];
        float4 p1 = *(const float4*)&g_P1[(size_t)r * H2 + j];
        float4 p2 = *(const float4*)&g_P2[(size_t)c * H2 + j];
        float4 wd = *(const float4*)&We1[(size_t)512 * H2 + j];
        float4 bb = *(const float4*)&be1[j];
        float d = dist_s[e];
        float vx = p1.x + p2.x + d * wd.x + bb.x;
        float vy = p1.y + p2.y + d * wd.y + bb.y;
        float vz = p1.z + p2.z + d * wd.z + bb.z;
        float vw = p1.w + p2.w + d * wd.w + bb.w;
#pragma unroll
        for (int k = 0; k < EDD; k++) {
            float f = ea_s[e * EDD + k];
            float4 w = *(const float4*)&w1e[k * H2 + j];
            vx += f * w.x; vy += f * w.y; vz += f * w.z; vw += f * w.w;
        }
        float4 o = make_float4(silu_f(vx), silu_f(vy), silu_f(vz), silu_f(vw));
        *(float4*)&t_s[e * H2 + j] = o;
    }
    __syncthreads();

    // Stage 2: LayerNorm over 512 (warp per edge, 4 edges/warp)
    int warp = tid >> 5, lane = tid & 31;
#pragma unroll
    for (int t = 0; t < 4; t++) {
        int e = warp * 4 + t;
        float s = 0.f, sq = 0.f, xv[16];
#pragma unroll
        for (int i = 0; i < 16; i++) {
            float x = t_s[e * H2 + lane + i * 32];
            xv[i] = x; s += x; sq += x * x;
        }
#pragma unroll
        for (int o = 16; o; o >>= 1) {
            s += __shfl_xor_sync(0xffffffffu, s, o);
            sq += __shfl_xor_sync(0xffffffffu, sq, o);
        }
        float mu = s * (1.f / H2);
        float var = sq * (1.f / H2) - mu * mu;
        float rs = rsqrtf(var + 1e-5f);
#pragma unroll
        for (int i = 0; i < 16; i++) {
            int k = lane + i * 32;
            t_s[e * H2 + k] = (xv[i] - mu) * rs * ge[k] + beln[k];
        }
    }
    __syncthreads();

    // Stage 3: m = silu(t @ W_e2 + b_e2) ; att partials
    int tx = tid & 63, ty = tid >> 6;
    int n0 = tx * 4, eb = ty * 8;
    float acc[8][4] = {};
#pragma unroll 4
    for (int k = 0; k < H2; k++) {
        float4 w = *(const float4*)&We2[(size_t)k * HH + n0];
#pragma unroll
        for (int i = 0; i < 8; i++) {
            float a = t_s[(eb + i) * H2 + k];
            acc[i][0] += a * w.x; acc[i][1] += a * w.y;
            acc[i][2] += a * w.z; acc[i][3] += a * w.w;
        }
    }
    {
        float4 bb2 = *(const float4*)&be2[n0];
        float4 wa4 = *(const float4*)&Wa[n0];
        float patt[8];
#pragma unroll
        for (int i = 0; i < 8; i++) {
            float m0 = silu_f(acc[i][0] + bb2.x);
            float m1 = silu_f(acc[i][1] + bb2.y);
            float m2 = silu_f(acc[i][2] + bb2.z);
            float m3 = silu_f(acc[i][3] + bb2.w);
            *(float4*)&m_s[(eb + i) * HH + n0] = make_float4(m0, m1, m2, m3);
            patt[i] = m0 * wa4.x + m1 * wa4.y + m2 * wa4.z + m3 * wa4.w;
        }
#pragma unroll
        for (int o = 16; o; o >>= 1)
#pragma unroll
            for (int i = 0; i < 8; i++) patt[i] += __shfl_xor_sync(0xffffffffu, patt[i], o);
        if (lane == 0)
#pragma unroll
            for (int i = 0; i < 8; i++) atomicAdd(&att_s[eb + i], patt[i]);
    }
    __syncthreads();
    if (tid < 32) att_s[tid] = sigm_f(att_s[tid] + ba[0]);
    __syncthreads();

    // Stage 4: coord_w = silu(m @ W_c1 + b_c1) . W_c2
    float acc2[8][4] = {};
#pragma unroll 4
    for (int k = 0; k < HH; k++) {
        float4 w = *(const float4*)&Wc1[(size_t)k * HH + n0];
#pragma unroll
        for (int i = 0; i < 8; i++) {
            float a = m_s[(eb + i) * HH + k];
            acc2[i][0] += a * w.x; acc2[i][1] += a * w.y;
            acc2[i][2] += a * w.z; acc2[i][3] += a * w.w;
        }
    }
    {
        float4 bc = *(const float4*)&bc1[n0];
        float4 wc = *(const float4*)&Wc2[n0];
        float pcw[8];
#pragma unroll
        for (int i = 0; i < 8; i++) {
            pcw[i] = silu_f(acc2[i][0] + bc.x) * wc.x + silu_f(acc2[i][1] + bc.y) * wc.y +
                     silu_f(acc2[i][2] + bc.z) * wc.z + silu_f(acc2[i][3] + bc.w) * wc.w;
        }
#pragma unroll
        for (int o = 16; o; o >>= 1)
#pragma unroll
            for (int i = 0; i < 8; i++) pcw[i] += __shfl_xor_sync(0xffffffffu, pcw[i], o);
        if (lane == 0)
#pragma unroll
            for (int i = 0; i < 8; i++) atomicAdd(&cw_s[eb + i], pcw[i]);
    }
    __syncthreads();

    // Stage 5: scatter
    {
        int n = tid;
#pragma unroll 4
        for (int e = 0; e < 32; e++)
            atomicAdd(&g_agg[(size_t)row_s[e] * HH + n], m_s[e * HH + n] * att_s[e]);
    }
    if (tid < 96) {
        int e = tid / 3, d = tid % 3;
        atomicAdd(&g_cagg[(size_t)row_s[e] * 3 + d], diff_s[e * 3 + d] * cw_s[e]);
    }
}

// ---------------------------------------------------------------- pos_new
__global__ void k_pos(const float* __restrict__ pos, float* __restrict__ outp) {
    int i = blockIdx.x * 256 + threadIdx.x;
    if (i < NN * 3) outp[i] = pos[i] + g_cagg[i];
}

// ---------------------------------------------------------------- node MLP part 1 (LN(silu([h,agg]@Wn1+bn1)))
__global__ __launch_bounds__(256) void k_node1(const float* __restrict__ h,
                                               const float* __restrict__ Wn1,
                                               const float* __restrict__ bn1,
                                               const float* __restrict__ gn,
                                               const float* __restrict__ bnln) {
    extern __shared__ float sm[];
    float* in_s = sm;            // 32*512
    float* v_s = sm + 32 * H2;   // 32*512
    int tid = threadIdx.x;
    int nb = blockIdx.x * 32;
    for (int i = tid; i < 32 * H2 / 4; i += 256) {
        int r = (i * 4) >> 9, c = (i * 4) & 511;
        int node = nb + r;
        float4 v = make_float4(0.f, 0.f, 0.f, 0.f);
        if (node < NN) {
            if (c < 256) v = *(const float4*)&h[(size_t)node * HH + c];
            else v = *(const float4*)&g_agg[(size_t)node * HH + (c - 256)];
        }
        *(float4*)&in_s[r * H2 + c] = v;
    }
    __syncthreads();
    int tx = tid & 63, ty = tid >> 6, eb = ty * 8;
    for (int ph = 0; ph < 2; ph++) {
        int n0 = ph * 256 + tx * 4;
        float acc[8][4] = {};
#pragma unroll 4
        for (int k = 0; k < H2; k++) {
            float4 w = *(const float4*)&Wn1[(size_t)k * H2 + n0];
#pragma unroll
            for (int i = 0; i < 8; i++) {
                float a = in_s[(eb + i) * H2 + k];
                acc[i][0] += a * w.x; acc[i][1] += a * w.y;
                acc[i][2] += a * w.z; acc[i][3] += a * w.w;
            }
        }
        float4 b4 = *(const float4*)&bn1[n0];
#pragma unroll
        for (int i = 0; i < 8; i++)
            *(float4*)&v_s[(eb + i) * H2 + n0] =
                make_float4(silu_f(acc[i][0] + b4.x), silu_f(acc[i][1] + b4.y),
                            silu_f(acc[i][2] + b4.z), silu_f(acc[i][3] + b4.w));
    }
    __syncthreads();
    int warp = tid >> 5, lane = tid & 31;
#pragma unroll
    for (int t = 0; t < 4; t++) {
        int r = warp * 4 + t;
        int node = nb + r;
        float s = 0.f, sq = 0.f, xv[16];
#pragma unroll
        for (int i = 0; i < 16; i++) {
            float x = v_s[r * H2 + lane + i * 32];
            xv[i] = x; s += x; sq += x * x;
        }
#pragma unroll
        for (int o = 16; o; o >>= 1) {
            s += __shfl_xor_sync(0xffffffffu, s, o);
            sq += __shfl_xor_sync(0xffffffffu, sq, o);
        }
        float mu = s * (1.f / H2);
        float var = sq * (1.f / H2) - mu * mu;
        float rs = rsqrtf(var + 1e-5f);
        if (node < NN)
#pragma unroll
            for (int i = 0; i < 16; i++) {
                int k = lane + i * 32;
                g_nln[(size_t)node * H2 + k] = (xv[i] - mu) * rs * gn[k] + bnln[k];
            }
    }
}

// ---------------------------------------------------------------- node MLP part 2 + outer LN -> out h
__global__ __launch_bounds__(256) void k_node2(const float* __restrict__ h,
                                               const float* __restrict__ Wn2,
                                               const float* __restrict__ bn2,
                                               const float* __restrict__ go,
                                               const float* __restrict__ boln,
                                               float* __restrict__ outh) {
    extern __shared__ float sm[];
    float* s_s = sm;             // 32*512
    float* hn_s = sm + 32 * H2;  // 32*256
    int tid = threadIdx.x;
    int nb = blockIdx.x * 32;
    for (int i = tid; i < 32 * H2 / 4; i += 256) {
        int r = (i * 4) >> 9, c = (i * 4) & 511;
        int node = nb + r;
        float4 v = make_float4(0.f, 0.f, 0.f, 0.f);
        if (node < NN) v = *(const float4*)&g_nln[(size_t)node * H2 + c];
        *(float4*)&s_s[r * H2 + c] = v;
    }
    __syncthreads();
    int tx = tid & 63, ty = tid >> 6;
    int n0 = tx * 4, eb = ty * 8;
    float acc[8][4] = {};
#pragma unroll 4
    for (int k = 0; k < H2; k++) {
        float4 w = *(const float4*)&Wn2[(size_t)k * HH + n0];
#pragma unroll
        for (int i = 0; i < 8; i++) {
            float a = s_s[(eb + i) * H2 + k];
            acc[i][0] += a * w.x; acc[i][1] += a * w.y;
            acc[i][2] += a * w.z; acc[i][3] += a * w.w;
        }
    }
    float4 b4 = *(const float4*)&bn2[n0];
#pragma unroll
    for (int i = 0; i < 8; i++) {
        int node = nb + eb + i;
        float4 hv = make_float4(0.f, 0.f, 0.f, 0.f);
        if (node < NN) hv = *(const float4*)&h[(size_t)node * HH + n0];
        *(float4*)&hn_s[(eb + i) * HH + n0] =
            make_float4(acc[i][0] + b4.x + hv.x, acc[i][1] + b4.y + hv.y,
                        acc[i][2] + b4.z + hv.z, acc[i][3] + b4.w + hv.w);
    }
    __syncthreads();
    int warp = tid >> 5, lane = tid & 31;
#pragma unroll
    for (int t = 0; t < 4; t++) {
        int r = warp * 4 + t;
        int node = nb + r;
        float s = 0.f, sq = 0.f, xv[8];
#pragma unroll
        for (int i = 0; i < 8; i++) {
            float x = hn_s[r * HH + lane + i * 32];
            xv[i] = x; s += x; sq += x * x;
        }
#pragma unroll
        for (int o = 16; o; o >>= 1) {
            s += __shfl_xor_sync(0xffffffffu, s, o);
            sq += __shfl_xor_sync(0xffffffffu, sq, o);
        }
        float mu = s * (1.f / HH);
        float var = sq * (1.f / HH) - mu * mu;
        float rs = rsqrtf(var + 1e-5f);
        if (node < NN)
#pragma unroll
            for (int i = 0; i < 8; i++) {
                int k = lane + i * 32;
                outh[(size_t)node * HH + k] = (xv[i] - mu) * rs * go[k] + boln[k];
            }
    }
}

// ---------------------------------------------------------------- feedback scatter: uagg += silu(d_new*Wf1+bf1), deg += 1
__global__ __launch_bounds__(256) void k_fb(const int* __restrict__ ei,
                                            const float* __restrict__ posn,
                                            const float* __restrict__ Wf1,
                                            const float* __restrict__ bf1) {
    int warp = threadIdx.x >> 5, lane = threadIdx.x & 31;
#pragma unroll
    for (int t = 0; t < 4; t++) {
        int e = blockIdx.x * 32 + warp * 4 + t;
        int r = ei[e], c = ei[EE + e];
        float dx = posn[r * 3 + 0] - posn[c * 3 + 0];
        float dy = posn[r * 3 + 1] - posn[c * 3 + 1];
        float dz = posn[r * 3 + 2] - posn[c * 3 + 2];
        float dn = fmaxf(sqrtf(dx * dx + dy * dy + dz * dz), 1e-5f);
#pragma unroll
        for (int j = lane; j < HH; j += 32) {
            float u = silu_f(dn * Wf1[j] + bf1[j]);
            atomicAdd(&g_uagg[(size_t)r * HH + j], u);
        }
        if (lane == 0) atomicAdd(&g_deg[r], 1.f);
    }
}

// ---------------------------------------------------------------- fb_agg = uagg @ Wf2 + deg*bf2 ; out h += 0.1*fb
__global__ __launch_bounds__(256) void k_fb2(const float* __restrict__ Wf2,
                                             const float* __restrict__ bf2,
                                             float* __restrict__ outh) {
    __shared__ float u_s[32 * HH];
    int tid = threadIdx.x;
    int nb = blockIdx.x * 32;
    for (int i = tid; i < 32 * HH / 4; i += 256) {
        int r = (i * 4) >> 8, c = (i * 4) & 255;
        int node = nb + r;
        float4 v = make_float4(0.f, 0.f, 0.f, 0.f);
        if (node < NN) v = *(const float4*)&g_uagg[(size_t)node * HH + c];
        *(float4*)&u_s[r * HH + c] = v;
    }
    __syncthreads();
    int tx = tid & 63, ty = tid >> 6;
    int n0 = tx * 4, eb = ty * 8;
    float acc[8][4] = {};
#pragma unroll 4
    for (int k = 0; k < HH; k++) {
        float4 w = *(const float4*)&Wf2[(size_t)k * HH + n0];
#pragma unroll
        for (int i = 0; i < 8; i++) {
            float a = u_s[(eb + i) * HH + k];
            acc[i][0] += a * w.x; acc[i][1] += a * w.y;
            acc[i][2] += a * w.z; acc[i][3] += a * w.w;
        }
    }
    float4 b4 = *(const float4*)&bf2[n0];
#pragma unroll
    for (int i = 0; i < 8; i++) {
        int node = nb + eb + i;
        if (node < NN) {
            float dg = g_deg[node];
            float4 o = *(float4*)&outh[(size_t)node * HH + n0];
            o.x += 0.1f * (acc[i][0] + dg * b4.x);
            o.y += 0.1f * (acc[i][1] + dg * b4.y);
            o.z += 0.1f * (acc[i][2] + dg * b4.z);
            o.w += 0.1f * (acc[i][3] + dg * b4.w);
            *(float4*)&outh[(size_t)node * HH + n0] = o;
        }
    }
}

// ---------------------------------------------------------------- launch
extern "C" void kernel_launch(void* const* d_in, const int* in_sizes, int n_in,
                              void* d_out, int out_size) {
    const float* h    = (const float*)d_in[0];
    const float* pos  = (const float*)d_in[1];
    const int*   ei   = (const int*)d_in[2];
    const float* ea   = (const float*)d_in[3];
    const float* We1  = (const float*)d_in[4];
    const float* be1  = (const float*)d_in[5];
    const float* ge   = (const float*)d_in[6];
    const float* beln = (const float*)d_in[7];
    const float* We2  = (const float*)d_in[8];
    const float* be2  = (const float*)d_in[9];
    const float* Wn1  = (const float*)d_in[10];
    const float* bn1  = (const float*)d_in[11];
    const float* gn   = (const float*)d_in[12];
    const float* bnln = (const float*)d_in[13];
    const float* Wn2  = (const float*)d_in[14];
    const float* bn2  = (const float*)d_in[15];
    const float* go   = (const float*)d_in[16];
    const float* boln = (const float*)d_in[17];
    const float* Wc1  = (const float*)d_in[18];
    const float* bc1  = (const float*)d_in[19];
    const float* Wc2  = (const float*)d_in[20];
    const float* Wa   = (const float*)d_in[21];
    const float* ba   = (const float*)d_in[22];
    const float* Wf1  = (const float*)d_in[23];
    const float* bf1  = (const float*)d_in[24];
    const float* Wf2  = (const float*)d_in[25];
    const float* bf2  = (const float*)d_in[26];

    float* outh = (float*)d_out;
    float* outp = outh + (size_t)NN * HH;

    const int SME_BYTES = SME_FLOATS * 4;                  // 127,616 B
    cudaFuncSetAttribute(k_edge, cudaFuncAttributeMaxDynamicSharedMemorySize, SME_BYTES);
    cudaFuncSetAttribute(k_node1, cudaFuncAttributeMaxDynamicSharedMemorySize, 32 * H2 * 2 * 4);
    cudaFuncSetAttribute(k_node2, cudaFuncAttributeMaxDynamicSharedMemorySize, (32 * H2 + 32 * HH) * 4);

    int nblk = (NN + 31) / 32;                             // 1563

    k_zero<<<(NN * HH) / 256, 256>>>();
    k_pre<<<dim3(nblk, 4), 256>>>(h, We1);
    k_edge<<<EE / 32, 256, SME_BYTES>>>(pos, ei, ea, We1, be1, ge, beln,
                                        We2, be2, Wc1, bc1, Wc2, Wa, ba);
    k_pos<<<(NN * 3 + 255) / 256, 256>>>(pos, outp);
    k_node1<<<nblk, 256, 32 * H2 * 2 * 4>>>(h, Wn1, bn1, gn, bnln);
    k_node2<<<nblk, 256, (32 * H2 + 32 * HH) * 4>>>(h, Wn2, bn2, go, boln, outh);
    k_fb<<<EE / 32, 256>>>(ei, outp, Wf1, bf1);
    k_fb2<<<nblk, 256>>>(Wf2, bf2, outh);
}

// round 2
// speedup vs baseline: 1.0865x; 1.0865x over previous
#include <cuda_runtime.h>
#include <math.h>

#define NN 50000
#define EE 800000
#define HH 256
#define H2 512
#define EDD 13

typedef unsigned long long ull;

// ---- device scratch ----
__device__ float g_P1[(size_t)NN * H2];
__device__ float g_P2[(size_t)NN * H2];
__device__ float g_agg[(size_t)NN * HH];
__device__ float g_cagg[(size_t)NN * 3];
__device__ float g_uagg[(size_t)NN * HH];
__device__ float g_deg[NN];
__device__ float g_nln[(size_t)NN * H2];
// paired-weight scratch (k-pairs interleaved per column)
__device__ float g_We1p[512 * 512];
__device__ float g_We2p[512 * 256];
__device__ float g_Wn1p[512 * 512];
__device__ float g_Wn2p[512 * 256];
__device__ float g_Wc1p[256 * 256];
__device__ float g_Wf2p[256 * 256];

__device__ __forceinline__ float silu_f(float x) { return x / (1.f + __expf(-x)); }
__device__ __forceinline__ float sigm_f(float x) { return 1.f / (1.f + __expf(-x)); }

__device__ __forceinline__ void fma2(ull& c, ull a, ull b) {
    asm("fma.rn.f32x2 %0, %1, %2, %0;" : "+l"(c) : "l"(a), "l"(b));
}
__device__ __forceinline__ float f2sum(ull v) {
    return __uint_as_float((unsigned)v) + __uint_as_float((unsigned)(v >> 32));
}

// ---------------------------------------------------------------- weight pair-packer
// Wp[(k/2)*2N + 2n + p] = W[(k+p)*N + n]
__global__ void k_pack(const float* __restrict__ W, float* __restrict__ Wp, int K, int N) {
    int idx = blockIdx.x * 256 + threadIdx.x;
    int tot = (K / 2) * N;
    if (idx >= tot) return;
    int k2 = idx / N, n = idx - k2 * N;
    Wp[(size_t)k2 * 2 * N + 2 * n]     = W[(size_t)(2 * k2) * N + n];
    Wp[(size_t)k2 * 2 * N + 2 * n + 1] = W[(size_t)(2 * k2 + 1) * N + n];
}

// ---------------------------------------------------------------- zero scratch
__global__ void k_zero() {
    size_t i = (size_t)blockIdx.x * 256 + threadIdx.x;
    g_agg[i] = 0.f;
    g_uagg[i] = 0.f;
    if (i < (size_t)NN * 3) g_cagg[i] = 0.f;
    if (i < NN) g_deg[i] = 0.f;
}

// ---------------------------------------------------------------- P1/P2 = h @ W_e1 halves (f32x2)
__global__ __launch_bounds__(256) void k_pre(const float* __restrict__ h) {
    __shared__ float hs[32 * HH];
    int tid = threadIdx.x;
    int nb = blockIdx.x * 32;
    for (int i = tid; i < 32 * HH / 4; i += 256) {
        int r = (i * 4) >> 8, c = (i * 4) & 255;
        int node = nb + r;
        float4 v = make_float4(0.f, 0.f, 0.f, 0.f);
        if (node < NN) v = *(const float4*)&h[(size_t)node * HH + c];
        *(float4*)&hs[r * HH + c] = v;
    }
    __syncthreads();
    int isP2 = blockIdx.y >> 1;
    int cb = (blockIdx.y & 1) * 256;
    const ull* Wp = (const ull*)g_We1p;
    float* outp = isP2 ? g_P2 : g_P1;
    int tx = tid & 63, ty = tid >> 6;
    int n0 = cb + tx * 4, e0 = ty * 8;
    int k2base = isP2 * (HH / 2);
    ull acc[8][4] = {};
#pragma unroll 2
    for (int k2 = 0; k2 < HH / 2; k2++) {
        const ull* wr = &Wp[(size_t)(k2base + k2) * H2 + n0];
        ulonglong2 q0 = *(const ulonglong2*)wr;
        ulonglong2 q1 = *(const ulonglong2*)(wr + 2);
#pragma unroll
        for (int i = 0; i < 8; i++) {
            ull a2 = *(const ull*)&hs[(e0 + i) * HH + 2 * k2];
            fma2(acc[i][0], a2, q0.x);
            fma2(acc[i][1], a2, q0.y);
            fma2(acc[i][2], a2, q1.x);
            fma2(acc[i][3], a2, q1.y);
        }
    }
#pragma unroll
    for (int i = 0; i < 8; i++) {
        int node = nb + e0 + i;
        if (node < NN)
            *(float4*)&outp[(size_t)node * H2 + n0] =
                make_float4(f2sum(acc[i][0]), f2sum(acc[i][1]),
                            f2sum(acc[i][2]), f2sum(acc[i][3]));
    }
}

// ---------------------------------------------------------------- fused edge kernel
static const int SME_FLOATS = 32 * H2 + 32 * HH + EDD * H2 + 32 * EDD + 32 + 96 + 32 + 32 + 64;

__global__ __launch_bounds__(256) void k_edge(
    const float* __restrict__ pos, const int* __restrict__ ei, const float* __restrict__ ea,
    const float* __restrict__ We1, const float* __restrict__ be1,
    const float* __restrict__ ge, const float* __restrict__ beln,
    const float* __restrict__ be2,
    const float* __restrict__ bc1, const float* __restrict__ Wc2,
    const float* __restrict__ Wa, const float* __restrict__ ba) {
    extern __shared__ float sm[];
    float* t_s = sm;                      // 32*512
    float* m_s = t_s + 32 * H2;           // 32*256
    float* w1e = m_s + 32 * HH;           // 13*512
    float* ea_s = w1e + EDD * H2;         // 32*13
    float* dist_s = ea_s + 32 * EDD;      // 32
    float* diff_s = dist_s + 32;          // 96
    float* att_s = diff_s + 96;           // 32
    float* cw_s = att_s + 32;             // 32
    int* row_s = (int*)(cw_s + 32);       // 32
    int* col_s = row_s + 32;              // 32

    int tid = threadIdx.x;
    int e0g = blockIdx.x * 32;

    for (int i = tid; i < EDD * H2 / 4; i += 256)
        *(float4*)&w1e[i * 4] = *(const float4*)&We1[(size_t)513 * H2 + i * 4];
    for (int i = tid; i < 32 * EDD; i += 256)
        ea_s[i] = ea[(size_t)e0g * EDD + i];
    if (tid < 32) {
        int e = e0g + tid;
        int r = ei[e], c = ei[EE + e];
        row_s[tid] = r; col_s[tid] = c;
        float dx = pos[r * 3 + 0] - pos[c * 3 + 0];
        float dy = pos[r * 3 + 1] - pos[c * 3 + 1];
        float dz = pos[r * 3 + 2] - pos[c * 3 + 2];
        diff_s[tid * 3 + 0] = dx; diff_s[tid * 3 + 1] = dy; diff_s[tid * 3 + 2] = dz;
        dist_s[tid] = fmaxf(sqrtf(dx * dx + dy * dy + dz * dz), 1e-5f);
        att_s[tid] = 0.f; cw_s[tid] = 0.f;
    }
    __syncthreads();

    // Stage 1: t_s = silu(P1[row] + P2[col] + dist*w_d + ea@W1e + b_e1)
    for (int idx = tid; idx < 32 * (H2 / 4); idx += 256) {
        int e = idx >> 7;
        int j = (idx & 127) * 4;
        int r = row_s[e], c = col_s[e];
        float4 p1 = *(const float4*)&g_P1[(size_t)r * H2 + j];
        float4 p2 = *(const float4*)&g_P2[(size_t)c * H2 + j];
        float4 wd = *(const float4*)&We1[(size_t)512 * H2 + j];
        float4 bb = *(const float4*)&be1[j];
        float d = dist_s[e];
        float vx = p1.x + p2.x + d * wd.x + bb.x;
        float vy = p1.y + p2.y + d * wd.y + bb.y;
        float vz = p1.z + p2.z + d * wd.z + bb.z;
        float vw = p1.w + p2.w + d * wd.w + bb.w;
#pragma unroll
        for (int k = 0; k < EDD; k++) {
            float f = ea_s[e * EDD + k];
            float4 w = *(const float4*)&w1e[k * H2 + j];
            vx += f * w.x; vy += f * w.y; vz += f * w.z; vw += f * w.w;
        }
        *(float4*)&t_s[e * H2 + j] =
            make_float4(silu_f(vx), silu_f(vy), silu_f(vz), silu_f(vw));
    }
    __syncthreads();

    // Stage 2: LayerNorm over 512 (warp per edge, 4 edges/warp)
    int warp = tid >> 5, lane = tid & 31;
#pragma unroll
    for (int t = 0; t < 4; t++) {
        int e = warp * 4 + t;
        float s = 0.f, sq = 0.f, xv[16];
#pragma unroll
        for (int i = 0; i < 16; i++) {
            float x = t_s[e * H2 + lane + i * 32];
            xv[i] = x; s += x; sq += x * x;
        }
#pragma unroll
        for (int o = 16; o; o >>= 1) {
            s += __shfl_xor_sync(0xffffffffu, s, o);
            sq += __shfl_xor_sync(0xffffffffu, sq, o);
        }
        float mu = s * (1.f / H2);
        float var = sq * (1.f / H2) - mu * mu;
        float rs = rsqrtf(var + 1e-5f);
#pragma unroll
        for (int i = 0; i < 16; i++) {
            int k = lane + i * 32;
            t_s[e * H2 + k] = (xv[i] - mu) * rs * ge[k] + beln[k];
        }
    }
    __syncthreads();

    // Stage 3: m = silu(t @ W_e2 + b_e2) via f32x2; att partials
    int tx = tid & 63, ty = tid >> 6;
    int n0 = tx * 4, eb = ty * 8;
    {
        const ull* Wp = (const ull*)g_We2p;
        ull acc[8][4] = {};
#pragma unroll 2
        for (int k2 = 0; k2 < H2 / 2; k2++) {
            const ull* wr = &Wp[(size_t)k2 * HH + n0];
            ulonglong2 q0 = *(const ulonglong2*)wr;
            ulonglong2 q1 = *(const ulonglong2*)(wr + 2);
#pragma unroll
            for (int i = 0; i < 8; i++) {
                ull a2 = *(const ull*)&t_s[(eb + i) * H2 + 2 * k2];
                fma2(acc[i][0], a2, q0.x);
                fma2(acc[i][1], a2, q0.y);
                fma2(acc[i][2], a2, q1.x);
                fma2(acc[i][3], a2, q1.y);
            }
        }
        float4 bb2 = *(const float4*)&be2[n0];
        float4 wa4 = *(const float4*)&Wa[n0];
        float patt[8];
#pragma unroll
        for (int i = 0; i < 8; i++) {
            float m0 = silu_f(f2sum(acc[i][0]) + bb2.x);
            float m1 = silu_f(f2sum(acc[i][1]) + bb2.y);
            float m2 = silu_f(f2sum(acc[i][2]) + bb2.z);
            float m3 = silu_f(f2sum(acc[i][3]) + bb2.w);
            *(float4*)&m_s[(eb + i) * HH + n0] = make_float4(m0, m1, m2, m3);
            patt[i] = m0 * wa4.x + m1 * wa4.y + m2 * wa4.z + m3 * wa4.w;
        }
#pragma unroll
        for (int o = 16; o; o >>= 1)
#pragma unroll
            for (int i = 0; i < 8; i++) patt[i] += __shfl_xor_sync(0xffffffffu, patt[i], o);
        if (lane == 0)
#pragma unroll
            for (int i = 0; i < 8; i++) atomicAdd(&att_s[eb + i], patt[i]);
    }
    __syncthreads();
    if (tid < 32) att_s[tid] = sigm_f(att_s[tid] + ba[0]);
    __syncthreads();

    // Stage 4: coord_w = silu(m @ W_c1 + b_c1) . W_c2  via f32x2
    {
        const ull* Wp = (const ull*)g_Wc1p;
        ull acc[8][4] = {};
#pragma unroll 2
        for (int k2 = 0; k2 < HH / 2; k2++) {
            const ull* wr = &Wp[(size_t)k2 * HH + n0];
            ulonglong2 q0 = *(const ulonglong2*)wr;
            ulonglong2 q1 = *(const ulonglong2*)(wr + 2);
#pragma unroll
            for (int i = 0; i < 8; i++) {
                ull a2 = *(const ull*)&m_s[(eb + i) * HH + 2 * k2];
                fma2(acc[i][0], a2, q0.x);
                fma2(acc[i][1], a2, q0.y);
                fma2(acc[i][2], a2, q1.x);
                fma2(acc[i][3], a2, q1.y);
            }
        }
        float4 bc = *(const float4*)&bc1[n0];
        float4 wc = *(const float4*)&Wc2[n0];
        float pcw[8];
#pragma unroll
        for (int i = 0; i < 8; i++) {
            pcw[i] = silu_f(f2sum(acc[i][0]) + bc.x) * wc.x +
                     silu_f(f2sum(acc[i][1]) + bc.y) * wc.y +
                     silu_f(f2sum(acc[i][2]) + bc.z) * wc.z +
                     silu_f(f2sum(acc[i][3]) + bc.w) * wc.w;
        }
#pragma unroll
        for (int o = 16; o; o >>= 1)
#pragma unroll
            for (int i = 0; i < 8; i++) pcw[i] += __shfl_xor_sync(0xffffffffu, pcw[i], o);
        if (lane == 0)
#pragma unroll
            for (int i = 0; i < 8; i++) atomicAdd(&cw_s[eb + i], pcw[i]);
    }
    __syncthreads();

    // Stage 5: scatter
    {
        int n = tid;
#pragma unroll 4
        for (int e = 0; e < 32; e++)
            atomicAdd(&g_agg[(size_t)row_s[e] * HH + n], m_s[e * HH + n] * att_s[e]);
    }
    if (tid < 96) {
        int e = tid / 3, d = tid % 3;
        atomicAdd(&g_cagg[(size_t)row_s[e] * 3 + d], diff_s[e * 3 + d] * cw_s[e]);
    }
}

// ---------------------------------------------------------------- pos_new
__global__ void k_pos(const float* __restrict__ pos, float* __restrict__ outp) {
    int i = blockIdx.x * 256 + threadIdx.x;
    if (i < NN * 3) outp[i] = pos[i] + g_cagg[i];
}

// ---------------------------------------------------------------- node MLP part 1
__global__ __launch_bounds__(256) void k_node1(const float* __restrict__ h,
                                               const float* __restrict__ bn1,
                                               const float* __restrict__ gn,
                                               const float* __restrict__ bnln) {
    extern __shared__ float sm[];
    float* in_s = sm;            // 32*512
    float* v_s = sm + 32 * H2;   // 32*512
    int tid = threadIdx.x;
    int nb = blockIdx.x * 32;
    for (int i = tid; i < 32 * H2 / 4; i += 256) {
        int r = (i * 4) >> 9, c = (i * 4) & 511;
        int node = nb + r;
        float4 v = make_float4(0.f, 0.f, 0.f, 0.f);
        if (node < NN) {
            if (c < 256) v = *(const float4*)&h[(size_t)node * HH + c];
            else v = *(const float4*)&g_agg[(size_t)node * HH + (c - 256)];
        }
        *(float4*)&in_s[r * H2 + c] = v;
    }
    __syncthreads();
    int tx = tid & 63, ty = tid >> 6, eb = ty * 8;
    const ull* Wp = (const ull*)g_Wn1p;
    for (int ph = 0; ph < 2; ph++) {
        int n0 = ph * 256 + tx * 4;
        ull acc[8][4] = {};
#pragma unroll 2
        for (int k2 = 0; k2 < H2 / 2; k2++) {
            const ull* wr = &Wp[(size_t)k2 * H2 + n0];
            ulonglong2 q0 = *(const ulonglong2*)wr;
            ulonglong2 q1 = *(const ulonglong2*)(wr + 2);
#pragma unroll
            for (int i = 0; i < 8; i++) {
                ull a2 = *(const ull*)&in_s[(eb + i) * H2 + 2 * k2];
                fma2(acc[i][0], a2, q0.x);
                fma2(acc[i][1], a2, q0.y);
                fma2(acc[i][2], a2, q1.x);
                fma2(acc[i][3], a2, q1.y);
            }
        }
        float4 b4 = *(const float4*)&bn1[n0];
#pragma unroll
        for (int i = 0; i < 8; i++)
            *(float4*)&v_s[(eb + i) * H2 + n0] =
                make_float4(silu_f(f2sum(acc[i][0]) + b4.x), silu_f(f2sum(acc[i][1]) + b4.y),
                            silu_f(f2sum(acc[i][2]) + b4.z), silu_f(f2sum(acc[i][3]) + b4.w));
    }
    __syncthreads();
    int warp = tid >> 5, lane = tid & 31;
#pragma unroll
    for (int t = 0; t < 4; t++) {
        int r = warp * 4 + t;
        int node = nb + r;
        float s = 0.f, sq = 0.f, xv[16];
#pragma unroll
        for (int i = 0; i < 16; i++) {
            float x = v_s[r * H2 + lane + i * 32];
            xv[i] = x; s += x; sq += x * x;
        }
#pragma unroll
        for (int o = 16; o; o >>= 1) {
            s += __shfl_xor_sync(0xffffffffu, s, o);
            sq += __shfl_xor_sync(0xffffffffu, sq, o);
        }
        float mu = s * (1.f / H2);
        float var = sq * (1.f / H2) - mu * mu;
        float rs = rsqrtf(var + 1e-5f);
        if (node < NN)
#pragma unroll
            for (int i = 0; i < 16; i++) {
                int k = lane + i * 32;
                g_nln[(size_t)node * H2 + k] = (xv[i] - mu) * rs * gn[k] + bnln[k];
            }
    }
}

// ---------------------------------------------------------------- node MLP part 2 + outer LN
__global__ __launch_bounds__(256) void k_node2(const float* __restrict__ h,
                                               const float* __restrict__ bn2,
                                               const float* __restrict__ go,
                                               const float* __restrict__ boln,
                                               float* __restrict__ outh) {
    extern __shared__ float sm[];
    float* s_s = sm;             // 32*512
    float* hn_s = sm + 32 * H2;  // 32*256
    int tid = threadIdx.x;
    int nb = blockIdx.x * 32;
    for (int i = tid; i < 32 * H2 / 4; i += 256) {
        int r = (i * 4) >> 9, c = (i * 4) & 511;
        int node = nb + r;
        float4 v = make_float4(0.f, 0.f, 0.f, 0.f);
        if (node < NN) v = *(const float4*)&g_nln[(size_t)node * H2 + c];
        *(float4*)&s_s[r * H2 + c] = v;
    }
    __syncthreads();
    int tx = tid & 63, ty = tid >> 6;
    int n0 = tx * 4, eb = ty * 8;
    const ull* Wp = (const ull*)g_Wn2p;
    ull acc[8][4] = {};
#pragma unroll 2
    for (int k2 = 0; k2 < H2 / 2; k2++) {
        const ull* wr = &Wp[(size_t)k2 * HH + n0];
        ulonglong2 q0 = *(const ulonglong2*)wr;
        ulonglong2 q1 = *(const ulonglong2*)(wr + 2);
#pragma unroll
        for (int i = 0; i < 8; i++) {
            ull a2 = *(const ull*)&s_s[(eb + i) * H2 + 2 * k2];
            fma2(acc[i][0], a2, q0.x);
            fma2(acc[i][1], a2, q0.y);
            fma2(acc[i][2], a2, q1.x);
            fma2(acc[i][3], a2, q1.y);
        }
    }
    float4 b4 = *(const float4*)&bn2[n0];
#pragma unroll
    for (int i = 0; i < 8; i++) {
        int node = nb + eb + i;
        float4 hv = make_float4(0.f, 0.f, 0.f, 0.f);
        if (node < NN) hv = *(const float4*)&h[(size_t)node * HH + n0];
        *(float4*)&hn_s[(eb + i) * HH + n0] =
            make_float4(f2sum(acc[i][0]) + b4.x + hv.x, f2sum(acc[i][1]) + b4.y + hv.y,
                        f2sum(acc[i][2]) + b4.z + hv.z, f2sum(acc[i][3]) + b4.w + hv.w);
    }
    __syncthreads();
    int warp = tid >> 5, lane = tid & 31;
#pragma unroll
    for (int t = 0; t < 4; t++) {
        int r = warp * 4 + t;
        int node = nb + r;
        float s = 0.f, sq = 0.f, xv[8];
#pragma unroll
        for (int i = 0; i < 8; i++) {
            float x = hn_s[r * HH + lane + i * 32];
            xv[i] = x; s += x; sq += x * x;
        }
#pragma unroll
        for (int o = 16; o; o >>= 1) {
            s += __shfl_xor_sync(0xffffffffu, s, o);
            sq += __shfl_xor_sync(0xffffffffu, sq, o);
        }
        float mu = s * (1.f / HH);
        float var = sq * (1.f / HH) - mu * mu;
        float rs = rsqrtf(var + 1e-5f);
        if (node < NN)
#pragma unroll
            for (int i = 0; i < 8; i++) {
                int k = lane + i * 32;
                outh[(size_t)node * HH + k] = (xv[i] - mu) * rs * go[k] + boln[k];
            }
    }
}

// ---------------------------------------------------------------- feedback scatter
__global__ __launch_bounds__(256) void k_fb(const int* __restrict__ ei,
                                            const float* __restrict__ posn,
                                            const float* __restrict__ Wf1,
                                            const float* __restrict__ bf1) {
    __shared__ float wf[HH], bf[HH];
    if (threadIdx.x < HH) {
        wf[threadIdx.x] = Wf1[threadIdx.x];
        bf[threadIdx.x] = bf1[threadIdx.x];
    }
    __syncthreads();
    int warp = threadIdx.x >> 5, lane = threadIdx.x & 31;
#pragma unroll
    for (int t = 0; t < 4; t++) {
        int e = blockIdx.x * 32 + warp * 4 + t;
        int r = ei[e], c = ei[EE + e];
        float dx = posn[r * 3 + 0] - posn[c * 3 + 0];
        float dy = posn[r * 3 + 1] - posn[c * 3 + 1];
        float dz = posn[r * 3 + 2] - posn[c * 3 + 2];
        float dn = fmaxf(sqrtf(dx * dx + dy * dy + dz * dz), 1e-5f);
#pragma unroll
        for (int j = lane; j < HH; j += 32) {
            float u = silu_f(dn * wf[j] + bf[j]);
            atomicAdd(&g_uagg[(size_t)r * HH + j], u);
        }
        if (lane == 0) atomicAdd(&g_deg[r], 1.f);
    }
}

// ---------------------------------------------------------------- fb_agg = uagg @ Wf2 + deg*bf2
__global__ __launch_bounds__(256) void k_fb2(const float* __restrict__ bf2,
                                             float* __restrict__ outh) {
    __shared__ float u_s[32 * HH];
    int tid = threadIdx.x;
    int nb = blockIdx.x * 32;
    for (int i = tid; i < 32 * HH / 4; i += 256) {
        int r = (i * 4) >> 8, c = (i * 4) & 255;
        int node = nb + r;
        float4 v = make_float4(0.f, 0.f, 0.f, 0.f);
        if (node < NN) v = *(const float4*)&g_uagg[(size_t)node * HH + c];
        *(float4*)&u_s[r * HH + c] = v;
    }
    __syncthreads();
    int tx = tid & 63, ty = tid >> 6;
    int n0 = tx * 4, eb = ty * 8;
    const ull* Wp = (const ull*)g_Wf2p;
    ull acc[8][4] = {};
#pragma unroll 2
    for (int k2 = 0; k2 < HH / 2; k2++) {
        const ull* wr = &Wp[(size_t)k2 * HH + n0];
        ulonglong2 q0 = *(const ulonglong2*)wr;
        ulonglong2 q1 = *(const ulonglong2*)(wr + 2);
#pragma unroll
        for (int i = 0; i < 8; i++) {
            ull a2 = *(const ull*)&u_s[(eb + i) * HH + 2 * k2];
            fma2(acc[i][0], a2, q0.x);
            fma2(acc[i][1], a2, q0.y);
            fma2(acc[i][2], a2, q1.x);
            fma2(acc[i][3], a2, q1.y);
        }
    }
    float4 b4 = *(const float4*)&bf2[n0];
#pragma unroll
    for (int i = 0; i < 8; i++) {
        int node = nb + eb + i;
        if (node < NN) {
            float dg = g_deg[node];
            float4 o = *(float4*)&outh[(size_t)node * HH + n0];
            o.x += 0.1f * (f2sum(acc[i][0]) + dg * b4.x);
            o.y += 0.1f * (f2sum(acc[i][1]) + dg * b4.y);
            o.z += 0.1f * (f2sum(acc[i][2]) + dg * b4.z);
            o.w += 0.1f * (f2sum(acc[i][3]) + dg * b4.w);
            *(float4*)&outh[(size_t)node * HH + n0] = o;
        }
    }
}

// ---------------------------------------------------------------- launch
extern "C" void kernel_launch(void* const* d_in, const int* in_sizes, int n_in,
                              void* d_out, int out_size) {
    const float* h    = (const float*)d_in[0];
    const float* pos  = (const float*)d_in[1];
    const int*   ei   = (const int*)d_in[2];
    const float* ea   = (const float*)d_in[3];
    const float* We1  = (const float*)d_in[4];
    const float* be1  = (const float*)d_in[5];
    const float* ge   = (const float*)d_in[6];
    const float* beln = (const float*)d_in[7];
    const float* We2  = (const float*)d_in[8];
    const float* be2  = (const float*)d_in[9];
    const float* Wn1  = (const float*)d_in[10];
    const float* bn1  = (const float*)d_in[11];
    const float* gn   = (const float*)d_in[12];
    const float* bnln = (const float*)d_in[13];
    const float* Wn2  = (const float*)d_in[14];
    const float* bn2  = (const float*)d_in[15];
    const float* go   = (const float*)d_in[16];
    const float* boln = (const float*)d_in[17];
    const float* Wc1  = (const float*)d_in[18];
    const float* bc1  = (const float*)d_in[19];
    const float* Wc2  = (const float*)d_in[20];
    const float* Wa   = (const float*)d_in[21];
    const float* ba   = (const float*)d_in[22];
    const float* Wf1  = (const float*)d_in[23];
    const float* bf1  = (const float*)d_in[24];
    const float* Wf2  = (const float*)d_in[25];
    const float* bf2  = (const float*)d_in[26];

    float* outh = (float*)d_out;
    float* outp = outh + (size_t)NN * HH;

    float *pWe1p, *pWe2p, *pWn1p, *pWn2p, *pWc1p, *pWf2p;
    cudaGetSymbolAddress((void**)&pWe1p, g_We1p);
    cudaGetSymbolAddress((void**)&pWe2p, g_We2p);
    cudaGetSymbolAddress((void**)&pWn1p, g_Wn1p);
    cudaGetSymbolAddress((void**)&pWn2p, g_Wn2p);
    cudaGetSymbolAddress((void**)&pWc1p, g_Wc1p);
    cudaGetSymbolAddress((void**)&pWf2p, g_Wf2p);

    const int SME_BYTES = SME_FLOATS * 4;
    cudaFuncSetAttribute(k_edge, cudaFuncAttributeMaxDynamicSharedMemorySize, SME_BYTES);
    cudaFuncSetAttribute(k_node1, cudaFuncAttributeMaxDynamicSharedMemorySize, 32 * H2 * 2 * 4);
    cudaFuncSetAttribute(k_node2, cudaFuncAttributeMaxDynamicSharedMemorySize, (32 * H2 + 32 * HH) * 4);

    int nblk = (NN + 31) / 32;
    #define PACKGRID(K, N) (((K / 2) * (N) + 255) / 256)

    // launch order chosen so ncu's -s 5 -c 1 slot lands on k_edge
    k_pack<<<PACKGRID(512, 512), 256>>>(We1, pWe1p, 512, 512);         // 0
    k_zero<<<(NN * HH) / 256, 256>>>();                                 // 1
    k_pre<<<dim3(nblk, 4), 256>>>(h);                                   // 2
    k_pack<<<PACKGRID(512, 256), 256>>>(We2, pWe2p, 512, 256);         // 3
    k_pack<<<PACKGRID(256, 256), 256>>>(Wc1, pWc1p, 256, 256);         // 4
    k_edge<<<EE / 32, 256, SME_BYTES>>>(pos, ei, ea, We1, be1, ge, beln, // 5
                                        be2, bc1, Wc2, Wa, ba);
    k_pos<<<(NN * 3 + 255) / 256, 256>>>(pos, outp);
    k_pack<<<PACKGRID(512, 512), 256>>>(Wn1, pWn1p, 512, 512);
    k_node1<<<nblk, 256, 32 * H2 * 2 * 4>>>(h, bn1, gn, bnln);
    k_pack<<<PACKGRID(512, 256), 256>>>(Wn2, pWn2p, 512, 256);
    k_node2<<<nblk, 256, (32 * H2 + 32 * HH) * 4>>>(h, bn2, go, boln, outh);
    k_fb<<<EE / 32, 256>>>(ei, outp, Wf1, bf1);
    k_pack<<<PACKGRID(256, 256), 256>>>(Wf2, pWf2p, 256, 256);
    k_fb2<<<nblk, 256>>>(bf2, outh);
}

// round 4
// speedup vs baseline: 1.6640x; 1.5314x over previous
#include <cuda_runtime.h>
#include <math.h>

#define NN 50000
#define EE 800000
#define HH 256
#define H2 512
#define EDD 13

typedef unsigned long long ull;

// ---- device scratch ----
__device__ float g_P1[(size_t)NN * H2];
__device__ float g_P2[(size_t)NN * H2];
__device__ float g_agg[(size_t)NN * HH];
__device__ float g_cagg[(size_t)NN * 3];
__device__ float g_uagg[(size_t)NN * HH];
__device__ float g_deg[NN];
__device__ float g_nln[(size_t)NN * H2];
__device__ float g_We1p[512 * 512];
__device__ float g_We2p[512 * 256];
__device__ float g_Wn1p[512 * 512];
__device__ float g_Wn2p[512 * 256];
__device__ float g_Wc1p[256 * 256];
__device__ float g_Wf2p[256 * 256];

__device__ __forceinline__ float silu_f(float x) { return x / (1.f + __expf(-x)); }
__device__ __forceinline__ float sigm_f(float x) { return 1.f / (1.f + __expf(-x)); }

__device__ __forceinline__ void fma2(ull& c, ull a, ull b) {
    asm("fma.rn.f32x2 %0, %1, %2, %0;" : "+l"(c) : "l"(a), "l"(b));
}
__device__ __forceinline__ float f2sum(ull v) {
    return __uint_as_float((unsigned)v) + __uint_as_float((unsigned)(v >> 32));
}

// ---------------------------------------------------------------- merged pair-packer
// Wp[(k/2)*2N + 2n + p] = W[(k+p)*N + n] for all 6 matrices in one launch.
__global__ void k_packall(const float* __restrict__ We1, const float* __restrict__ We2,
                          const float* __restrict__ Wn1, const float* __restrict__ Wn2,
                          const float* __restrict__ Wc1, const float* __restrict__ Wf2) {
    int b = blockIdx.x;
    const float* W; float* Wp; int N, base;
    if (b < 512)        { W = We1; Wp = g_We1p; N = 512; base = 0; }
    else if (b < 768)   { W = We2; Wp = g_We2p; N = 256; base = 512; }
    else if (b < 1280)  { W = Wn1; Wp = g_Wn1p; N = 512; base = 768; }
    else if (b < 1536)  { W = Wn2; Wp = g_Wn2p; N = 256; base = 1280; }
    else if (b < 1664)  { W = Wc1; Wp = g_Wc1p; N = 256; base = 1536; }
    else                { W = Wf2; Wp = g_Wf2p; N = 256; base = 1664; }
    int idx = (b - base) * 256 + threadIdx.x;
    int k2 = idx / N, n = idx - k2 * N;
    Wp[(size_t)k2 * 2 * N + 2 * n]     = W[(size_t)(2 * k2) * N + n];
    Wp[(size_t)k2 * 2 * N + 2 * n + 1] = W[(size_t)(2 * k2 + 1) * N + n];
}

// ---------------------------------------------------------------- zero scratch
__global__ void k_zero() {
    size_t i = (size_t)blockIdx.x * 256 + threadIdx.x;
    g_agg[i] = 0.f;
    g_uagg[i] = 0.f;
    if (i < (size_t)NN * 3) g_cagg[i] = 0.f;
    if (i < NN) g_deg[i] = 0.f;
}

// ---------------------------------------------------------------- P1/P2 = h @ W_e1 halves
__global__ __launch_bounds__(256) void k_pre(const float* __restrict__ h) {
    __shared__ float hs[32 * HH];
    int tid = threadIdx.x;
    int nb = blockIdx.x * 32;
    for (int i = tid; i < 32 * HH / 4; i += 256) {
        int r = (i * 4) >> 8, c = (i * 4) & 255;
        int node = nb + r;
        float4 v = make_float4(0.f, 0.f, 0.f, 0.f);
        if (node < NN) v = *(const float4*)&h[(size_t)node * HH + c];
        *(float4*)&hs[r * HH + c] = v;
    }
    __syncthreads();
    int isP2 = blockIdx.y >> 1;
    int cb = (blockIdx.y & 1) * 256;
    const ull* Wp = (const ull*)g_We1p;
    float* outp = isP2 ? g_P2 : g_P1;
    int tx = tid & 63, ty = tid >> 6;
    int n0 = cb + tx * 4, e0 = ty * 8;
    int k2base = isP2 * (HH / 2);
    ull acc[8][4] = {};
#pragma unroll 4
    for (int k2 = 0; k2 < HH / 2; k2++) {
        const ull* wr = &Wp[(size_t)(k2base + k2) * H2 + n0];
        ulonglong2 q0 = *(const ulonglong2*)wr;
        ulonglong2 q1 = *(const ulonglong2*)(wr + 2);
#pragma unroll
        for (int i = 0; i < 8; i++) {
            ull a2 = *(const ull*)&hs[(e0 + i) * HH + 2 * k2];
            fma2(acc[i][0], a2, q0.x);
            fma2(acc[i][1], a2, q0.y);
            fma2(acc[i][2], a2, q1.x);
            fma2(acc[i][3], a2, q1.y);
        }
    }
#pragma unroll
    for (int i = 0; i < 8; i++) {
        int node = nb + e0 + i;
        if (node < NN)
            *(float4*)&outp[(size_t)node * H2 + n0] =
                make_float4(f2sum(acc[i][0]), f2sum(acc[i][1]),
                            f2sum(acc[i][2]), f2sum(acc[i][3]));
    }
}

// ---------------------------------------------------------------- fused edge kernel (2 blocks/SM)
static const int SME_FLOATS = 32 * H2 + EDD * H2 + 32 * EDD + 32 + 96 + 32 + 32 + 64;

__global__ __launch_bounds__(256, 2) void k_edge(
    const float* __restrict__ pos, const int* __restrict__ ei, const float* __restrict__ ea,
    const float* __restrict__ We1, const float* __restrict__ be1,
    const float* __restrict__ ge, const float* __restrict__ beln,
    const float* __restrict__ be2,
    const float* __restrict__ bc1, const float* __restrict__ Wc2,
    const float* __restrict__ Wa, const float* __restrict__ ba) {
    extern __shared__ float sm[];
    float* t_s = sm;                      // 32*512  (front 32*256 reused for m)
    float* w1e = t_s + 32 * H2;           // 13*512
    float* ea_s = w1e + EDD * H2;         // 32*13
    float* dist_s = ea_s + 32 * EDD;      // 32
    float* diff_s = dist_s + 32;          // 96
    float* att_s = diff_s + 96;           // 32
    float* cw_s = att_s + 32;             // 32
    int* row_s = (int*)(cw_s + 32);       // 32
    int* col_s = row_s + 32;              // 32
    float* m_s = t_s;                     // alias (valid after stage 3)

    int tid = threadIdx.x;
    int e0g = blockIdx.x * 32;

    for (int i = tid; i < EDD * H2 / 4; i += 256)
        *(float4*)&w1e[i * 4] = *(const float4*)&We1[(size_t)513 * H2 + i * 4];
    for (int i = tid; i < 32 * EDD; i += 256)
        ea_s[i] = ea[(size_t)e0g * EDD + i];
    if (tid < 32) {
        int e = e0g + tid;
        int r = ei[e], c = ei[EE + e];
        row_s[tid] = r; col_s[tid] = c;
        float dx = pos[r * 3 + 0] - pos[c * 3 + 0];
        float dy = pos[r * 3 + 1] - pos[c * 3 + 1];
        float dz = pos[r * 3 + 2] - pos[c * 3 + 2];
        diff_s[tid * 3 + 0] = dx; diff_s[tid * 3 + 1] = dy; diff_s[tid * 3 + 2] = dz;
        dist_s[tid] = fmaxf(sqrtf(dx * dx + dy * dy + dz * dz), 1e-5f);
        att_s[tid] = 0.f; cw_s[tid] = 0.f;
    }
    __syncthreads();

    // Stage 1: t_s = silu(P1[row] + P2[col] + dist*w_d + ea@W1e + b_e1)
    for (int idx = tid; idx < 32 * (H2 / 4); idx += 256) {
        int e = idx >> 7;
        int j = (idx & 127) * 4;
        int r = row_s[e], c = col_s[e];
        float4 p1 = *(const float4*)&g_P1[(size_t)r * H2 + j];
        float4 p2 = *(const float4*)&g_P2[(size_t)c * H2 + j];
        float4 wd = *(const float4*)&We1[(size_t)512 * H2 + j];
        float4 bb = *(const float4*)&be1[j];
        float d = dist_s[e];
        float vx = p1.x + p2.x + d * wd.x + bb.x;
        float vy = p1.y + p2.y + d * wd.y + bb.y;
        float vz = p1.z + p2.z + d * wd.z + bb.z;
        float vw = p1.w + p2.w + d * wd.w + bb.w;
#pragma unroll
        for (int k = 0; k < EDD; k++) {
            float f = ea_s[e * EDD + k];
            float4 w = *(const float4*)&w1e[k * H2 + j];
            vx += f * w.x; vy += f * w.y; vz += f * w.z; vw += f * w.w;
        }
        *(float4*)&t_s[e * H2 + j] =
            make_float4(silu_f(vx), silu_f(vy), silu_f(vz), silu_f(vw));
    }
    __syncthreads();

    // Stage 2: LayerNorm over 512
    int warp = tid >> 5, lane = tid & 31;
#pragma unroll
    for (int t = 0; t < 4; t++) {
        int e = warp * 4 + t;
        float s = 0.f, sq = 0.f, xv[16];
#pragma unroll
        for (int i = 0; i < 16; i++) {
            float x = t_s[e * H2 + lane + i * 32];
            xv[i] = x; s += x; sq += x * x;
        }
#pragma unroll
        for (int o = 16; o; o >>= 1) {
            s += __shfl_xor_sync(0xffffffffu, s, o);
            sq += __shfl_xor_sync(0xffffffffu, sq, o);
        }
        float mu = s * (1.f / H2);
        float var = sq * (1.f / H2) - mu * mu;
        float rs = rsqrtf(var + 1e-5f);
#pragma unroll
        for (int i = 0; i < 16; i++) {
            int k = lane + i * 32;
            t_s[e * H2 + k] = (xv[i] - mu) * rs * ge[k] + beln[k];
        }
    }
    __syncthreads();

    // Stage 3: m = silu(t @ W_e2 + b_e2); hold m in regs, write after sync
    int tx = tid & 63, ty = tid >> 6;
    int n0 = tx * 4, eb = ty * 8;
    float mreg[8][4];
    {
        const ull* Wp = (const ull*)g_We2p;
        ull acc[8][4] = {};
#pragma unroll 4
        for (int k2 = 0; k2 < H2 / 2; k2++) {
            const ull* wr = &Wp[(size_t)k2 * HH + n0];
            ulonglong2 q0 = *(const ulonglong2*)wr;
            ulonglong2 q1 = *(const ulonglong2*)(wr + 2);
#pragma unroll
            for (int i = 0; i < 8; i++) {
                ull a2 = *(const ull*)&t_s[(eb + i) * H2 + 2 * k2];
                fma2(acc[i][0], a2, q0.x);
                fma2(acc[i][1], a2, q0.y);
                fma2(acc[i][2], a2, q1.x);
                fma2(acc[i][3], a2, q1.y);
            }
        }
        float4 bb2 = *(const float4*)&be2[n0];
        float4 wa4 = *(const float4*)&Wa[n0];
        float patt[8];
#pragma unroll
        for (int i = 0; i < 8; i++) {
            mreg[i][0] = silu_f(f2sum(acc[i][0]) + bb2.x);
            mreg[i][1] = silu_f(f2sum(acc[i][1]) + bb2.y);
            mreg[i][2] = silu_f(f2sum(acc[i][2]) + bb2.z);
            mreg[i][3] = silu_f(f2sum(acc[i][3]) + bb2.w);
            patt[i] = mreg[i][0] * wa4.x + mreg[i][1] * wa4.y +
                      mreg[i][2] * wa4.z + mreg[i][3] * wa4.w;
        }
#pragma unroll
        for (int o = 16; o; o >>= 1)
#pragma unroll
            for (int i = 0; i < 8; i++) patt[i] += __shfl_xor_sync(0xffffffffu, patt[i], o);
        if (lane == 0)
#pragma unroll
            for (int i = 0; i < 8; i++) atomicAdd(&att_s[eb + i], patt[i]);
    }
    __syncthreads();   // all reads of t_s complete
#pragma unroll
    for (int i = 0; i < 8; i++)
        *(float4*)&m_s[(eb + i) * HH + n0] =
            make_float4(mreg[i][0], mreg[i][1], mreg[i][2], mreg[i][3]);
    if (tid < 32) att_s[tid] = sigm_f(att_s[tid] + ba[0]);   // atomics done pre-sync
    __syncthreads();

    // Stage 4: coord_w = silu(m @ W_c1 + b_c1) . W_c2
    {
        const ull* Wp = (const ull*)g_Wc1p;
        ull acc[8][4] = {};
#pragma unroll 4
        for (int k2 = 0; k2 < HH / 2; k2++) {
            const ull* wr = &Wp[(size_t)k2 * HH + n0];
            ulonglong2 q0 = *(const ulonglong2*)wr;
            ulonglong2 q1 = *(const ulonglong2*)(wr + 2);
#pragma unroll
            for (int i = 0; i < 8; i++) {
                ull a2 = *(const ull*)&m_s[(eb + i) * HH + 2 * k2];
                fma2(acc[i][0], a2, q0.x);
                fma2(acc[i][1], a2, q0.y);
                fma2(acc[i][2], a2, q1.x);
                fma2(acc[i][3], a2, q1.y);
            }
        }
        float4 bc = *(const float4*)&bc1[n0];
        float4 wc = *(const float4*)&Wc2[n0];
        float pcw[8];
#pragma unroll
        for (int i = 0; i < 8; i++) {
            pcw[i] = silu_f(f2sum(acc[i][0]) + bc.x) * wc.x +
                     silu_f(f2sum(acc[i][1]) + bc.y) * wc.y +
                     silu_f(f2sum(acc[i][2]) + bc.z) * wc.z +
                     silu_f(f2sum(acc[i][3]) + bc.w) * wc.w;
        }
#pragma unroll
        for (int o = 16; o; o >>= 1)
#pragma unroll
            for (int i = 0; i < 8; i++) pcw[i] += __shfl_xor_sync(0xffffffffu, pcw[i], o);
        if (lane == 0)
#pragma unroll
            for (int i = 0; i < 8; i++) atomicAdd(&cw_s[eb + i], pcw[i]);
    }
    __syncthreads();

    // Stage 5: scatter
    {
        int n = tid;
#pragma unroll 4
        for (int e = 0; e < 32; e++)
            atomicAdd(&g_agg[(size_t)row_s[e] * HH + n], m_s[e * HH + n] * att_s[e]);
    }
    if (tid < 96) {
        int e = tid / 3, d = tid % 3;
        atomicAdd(&g_cagg[(size_t)row_s[e] * 3 + d], diff_s[e * 3 + d] * cw_s[e]);
    }
}

// ---------------------------------------------------------------- pos_new
__global__ void k_pos(const float* __restrict__ pos, float* __restrict__ outp) {
    int i = blockIdx.x * 256 + threadIdx.x;
    if (i < NN * 3) outp[i] = pos[i] + g_cagg[i];
}

// ---------------------------------------------------------------- node MLP part 1 (64KB smem, 2 blk/SM)
__global__ __launch_bounds__(256, 2) void k_node1(const float* __restrict__ h,
                                                  const float* __restrict__ bn1,
                                                  const float* __restrict__ gn,
                                                  const float* __restrict__ bnln) {
    extern __shared__ float sm[];
    float* in_s = sm;            // 32*512, later reused for v
    int tid = threadIdx.x;
    int nb = blockIdx.x * 32;
    for (int i = tid; i < 32 * H2 / 4; i += 256) {
        int r = (i * 4) >> 9, c = (i * 4) & 511;
        int node = nb + r;
        float4 v = make_float4(0.f, 0.f, 0.f, 0.f);
        if (node < NN) {
            if (c < 256) v = *(const float4*)&h[(size_t)node * HH + c];
            else v = *(const float4*)&g_agg[(size_t)node * HH + (c - 256)];
        }
        *(float4*)&in_s[r * H2 + c] = v;
    }
    __syncthreads();
    int tx = tid & 63, ty = tid >> 6, eb = ty * 8;
    const ull* Wp = (const ull*)g_Wn1p;
    float v0[8][4], v1[8][4];
    for (int ph = 0; ph < 2; ph++) {
        int n0 = ph * 256 + tx * 4;
        ull acc[8][4] = {};
#pragma unroll 4
        for (int k2 = 0; k2 < H2 / 2; k2++) {
            const ull* wr = &Wp[(size_t)k2 * H2 + n0];
            ulonglong2 q0 = *(const ulonglong2*)wr;
            ulonglong2 q1 = *(const ulonglong2*)(wr + 2);
#pragma unroll
            for (int i = 0; i < 8; i++) {
                ull a2 = *(const ull*)&in_s[(eb + i) * H2 + 2 * k2];
                fma2(acc[i][0], a2, q0.x);
                fma2(acc[i][1], a2, q0.y);
                fma2(acc[i][2], a2, q1.x);
                fma2(acc[i][3], a2, q1.y);
            }
        }
        float4 b4 = *(const float4*)&bn1[n0];
        float (*vv)[4] = ph ? v1 : v0;
#pragma unroll
        for (int i = 0; i < 8; i++) {
            vv[i][0] = silu_f(f2sum(acc[i][0]) + b4.x);
            vv[i][1] = silu_f(f2sum(acc[i][1]) + b4.y);
            vv[i][2] = silu_f(f2sum(acc[i][2]) + b4.z);
            vv[i][3] = silu_f(f2sum(acc[i][3]) + b4.w);
        }
    }
    __syncthreads();   // all GEMM reads of in_s done
#pragma unroll
    for (int i = 0; i < 8; i++) {
        *(float4*)&in_s[(eb + i) * H2 + tx * 4] =
            make_float4(v0[i][0], v0[i][1], v0[i][2], v0[i][3]);
        *(float4*)&in_s[(eb + i) * H2 + 256 + tx * 4] =
            make_float4(v1[i][0], v1[i][1], v1[i][2], v1[i][3]);
    }
    __syncthreads();
    int warp = tid >> 5, lane = tid & 31;
#pragma unroll
    for (int t = 0; t < 4; t++) {
        int r = warp * 4 + t;
        int node = nb + r;
        float s = 0.f, sq = 0.f, xv[16];
#pragma unroll
        for (int i = 0; i < 16; i++) {
            float x = in_s[r * H2 + lane + i * 32];
            xv[i] = x; s += x; sq += x * x;
        }
#pragma unroll
        for (int o = 16; o; o >>= 1) {
            s += __shfl_xor_sync(0xffffffffu, s, o);
            sq += __shfl_xor_sync(0xffffffffu, sq, o);
        }
        float mu = s * (1.f / H2);
        float var = sq * (1.f / H2) - mu * mu;
        float rs = rsqrtf(var + 1e-5f);
        if (node < NN)
#pragma unroll
            for (int i = 0; i < 16; i++) {
                int k = lane + i * 32;
                g_nln[(size_t)node * H2 + k] = (xv[i] - mu) * rs * gn[k] + bnln[k];
            }
    }
}

// ---------------------------------------------------------------- node MLP part 2 + outer LN (64KB, 2 blk/SM)
__global__ __launch_bounds__(256, 2) void k_node2(const float* __restrict__ h,
                                                  const float* __restrict__ bn2,
                                                  const float* __restrict__ go,
                                                  const float* __restrict__ boln,
                                                  float* __restrict__ outh) {
    extern __shared__ float sm[];
    float* s_s = sm;             // 32*512; front 32*256 reused for hn
    float* hn_s = sm;
    int tid = threadIdx.x;
    int nb = blockIdx.x * 32;
    for (int i = tid; i < 32 * H2 / 4; i += 256) {
        int r = (i * 4) >> 9, c = (i * 4) & 511;
        int node = nb + r;
        float4 v = make_float4(0.f, 0.f, 0.f, 0.f);
        if (node < NN) v = *(const float4*)&g_nln[(size_t)node * H2 + c];
        *(float4*)&s_s[r * H2 + c] = v;
    }
    __syncthreads();
    int tx = tid & 63, ty = tid >> 6;
    int n0 = tx * 4, eb = ty * 8;
    const ull* Wp = (const ull*)g_Wn2p;
    ull acc[8][4] = {};
#pragma unroll 4
    for (int k2 = 0; k2 < H2 / 2; k2++) {
        const ull* wr = &Wp[(size_t)k2 * HH + n0];
        ulonglong2 q0 = *(const ulonglong2*)wr;
        ulonglong2 q1 = *(const ulonglong2*)(wr + 2);
#pragma unroll
        for (int i = 0; i < 8; i++) {
            ull a2 = *(const ull*)&s_s[(eb + i) * H2 + 2 * k2];
            fma2(acc[i][0], a2, q0.x);
            fma2(acc[i][1], a2, q0.y);
            fma2(acc[i][2], a2, q1.x);
            fma2(acc[i][3], a2, q1.y);
        }
    }
    float4 b4 = *(const float4*)&bn2[n0];
    float hn[8][4];
#pragma unroll
    for (int i = 0; i < 8; i++) {
        int node = nb + eb + i;
        float4 hv = make_float4(0.f, 0.f, 0.f, 0.f);
        if (node < NN) hv = *(const float4*)&h[(size_t)node * HH + n0];
        hn[i][0] = f2sum(acc[i][0]) + b4.x + hv.x;
        hn[i][1] = f2sum(acc[i][1]) + b4.y + hv.y;
        hn[i][2] = f2sum(acc[i][2]) + b4.z + hv.z;
        hn[i][3] = f2sum(acc[i][3]) + b4.w + hv.w;
    }
    __syncthreads();   // all reads of s_s done
#pragma unroll
    for (int i = 0; i < 8; i++)
        *(float4*)&hn_s[(eb + i) * HH + n0] =
            make_float4(hn[i][0], hn[i][1], hn[i][2], hn[i][3]);
    __syncthreads();
    int warp = tid >> 5, lane = tid & 31;
#pragma unroll
    for (int t = 0; t < 4; t++) {
        int r = warp * 4 + t;
        int node = nb + r;
        float s = 0.f, sq = 0.f, xv[8];
#pragma unroll
        for (int i = 0; i < 8; i++) {
            float x = hn_s[r * HH + lane + i * 32];
            xv[i] = x; s += x; sq += x * x;
        }
#pragma unroll
        for (int o = 16; o; o >>= 1) {
            s += __shfl_xor_sync(0xffffffffu, s, o);
            sq += __shfl_xor_sync(0xffffffffu, sq, o);
        }
        float mu = s * (1.f / HH);
        float var = sq * (1.f / HH) - mu * mu;
        float rs = rsqrtf(var + 1e-5f);
        if (node < NN)
#pragma unroll
            for (int i = 0; i < 8; i++) {
                int k = lane + i * 32;
                outh[(size_t)node * HH + k] = (xv[i] - mu) * rs * go[k] + boln[k];
            }
    }
}

// ---------------------------------------------------------------- feedback scatter
__global__ __launch_bounds__(256) void k_fb(const int* __restrict__ ei,
                                            const float* __restrict__ posn,
                                            const float* __restrict__ Wf1,
                                            const float* __restrict__ bf1) {
    __shared__ float wf[HH], bf[HH];
    if (threadIdx.x < HH) {
        wf[threadIdx.x] = Wf1[threadIdx.x];
        bf[threadIdx.x] = bf1[threadIdx.x];
    }
    __syncthreads();
    int warp = threadIdx.x >> 5, lane = threadIdx.x & 31;
#pragma unroll
    for (int t = 0; t < 4; t++) {
        int e = blockIdx.x * 32 + warp * 4 + t;
        int r = ei[e], c = ei[EE + e];
        float dx = posn[r * 3 + 0] - posn[c * 3 + 0];
        float dy = posn[r * 3 + 1] - posn[c * 3 + 1];
        float dz = posn[r * 3 + 2] - posn[c * 3 + 2];
        float dn = fmaxf(sqrtf(dx * dx + dy * dy + dz * dz), 1e-5f);
#pragma unroll
        for (int j = lane; j < HH; j += 32) {
            float u = silu_f(dn * wf[j] + bf[j]);
            atomicAdd(&g_uagg[(size_t)r * HH + j], u);
        }
        if (lane == 0) atomicAdd(&g_deg[r], 1.f);
    }
}

// ---------------------------------------------------------------- fb_agg = uagg @ Wf2 + deg*bf2
__global__ __launch_bounds__(256) void k_fb2(const float* __restrict__ bf2,
                                             float* __restrict__ outh) {
    __shared__ float u_s[32 * HH];
    int tid = threadIdx.x;
    int nb = blockIdx.x * 32;
    for (int i = tid; i < 32 * HH / 4; i += 256) {
        int r = (i * 4) >> 8, c = (i * 4) & 255;
        int node = nb + r;
        float4 v = make_float4(0.f, 0.f, 0.f, 0.f);
        if (node < NN) v = *(const float4*)&g_uagg[(size_t)node * HH + c];
        *(float4*)&u_s[r * HH + c] = v;
    }
    __syncthreads();
    int tx = tid & 63, ty = tid >> 6;
    int n0 = tx * 4, eb = ty * 8;
    const ull* Wp = (const ull*)g_Wf2p;
    ull acc[8][4] = {};
#pragma unroll 4
    for (int k2 = 0; k2 < HH / 2; k2++) {
        const ull* wr = &Wp[(size_t)k2 * HH + n0];
        ulonglong2 q0 = *(const ulonglong2*)wr;
        ulonglong2 q1 = *(const ulonglong2*)(wr + 2);
#pragma unroll
        for (int i = 0; i < 8; i++) {
            ull a2 = *(const ull*)&u_s[(eb + i) * HH + 2 * k2];
            fma2(acc[i][0], a2, q0.x);
            fma2(acc[i][1], a2, q0.y);
            fma2(acc[i][2], a2, q1.x);
            fma2(acc[i][3], a2, q1.y);
        }
    }
    float4 b4 = *(const float4*)&bf2[n0];
#pragma unroll
    for (int i = 0; i < 8; i++) {
        int node = nb + eb + i;
        if (node < NN) {
            float dg = g_deg[node];
            float4 o = *(float4*)&outh[(size_t)node * HH + n0];
            o.x += 0.1f * (f2sum(acc[i][0]) + dg * b4.x);
            o.y += 0.1f * (f2sum(acc[i][1]) + dg * b4.y);
            o.z += 0.1f * (f2sum(acc[i][2]) + dg * b4.z);
            o.w += 0.1f * (f2sum(acc[i][3]) + dg * b4.w);
            *(float4*)&outh[(size_t)node * HH + n0] = o;
        }
    }
}

// ---------------------------------------------------------------- launch
extern "C" void kernel_launch(void* const* d_in, const int* in_sizes, int n_in,
                              void* d_out, int out_size) {
    const float* h    = (const float*)d_in[0];
    const float* pos  = (const float*)d_in[1];
    const int*   ei   = (const int*)d_in[2];
    const float* ea   = (const float*)d_in[3];
    const float* We1  = (const float*)d_in[4];
    const float* be1  = (const float*)d_in[5];
    const float* ge   = (const float*)d_in[6];
    const float* beln = (const float*)d_in[7];
    const float* We2  = (const float*)d_in[8];
    const float* be2  = (const float*)d_in[9];
    const float* Wn1  = (const float*)d_in[10];
    const float* bn1  = (const float*)d_in[11];
    const float* gn   = (const float*)d_in[12];
    const float* bnln = (const float*)d_in[13];
    const float* Wn2  = (const float*)d_in[14];
    const float* bn2  = (const float*)d_in[15];
    const float* go   = (const float*)d_in[16];
    const float* boln = (const float*)d_in[17];
    const float* Wc1  = (const float*)d_in[18];
    const float* bc1  = (const float*)d_in[19];
    const float* Wc2  = (const float*)d_in[20];
    const float* Wa   = (const float*)d_in[21];
    const float* ba   = (const float*)d_in[22];
    const float* Wf1  = (const float*)d_in[23];
    const float* bf1  = (const float*)d_in[24];
    const float* Wf2  = (const float*)d_in[25];
    const float* bf2  = (const float*)d_in[26];

    float* outh = (float*)d_out;
    float* outp = outh + (size_t)NN * HH;

    const int SME_BYTES = SME_FLOATS * 4;               // ~94.8 KB
    cudaFuncSetAttribute(k_edge, cudaFuncAttributeMaxDynamicSharedMemorySize, SME_BYTES);
    cudaFuncSetAttribute(k_node1, cudaFuncAttributeMaxDynamicSharedMemorySize, 32 * H2 * 4);
    cudaFuncSetAttribute(k_node2, cudaFuncAttributeMaxDynamicSharedMemorySize, 32 * H2 * 4);

    int nblk = (NN + 31) / 32;

    // ncu profiles launch index 3 -> k_edge
    k_zero<<<(NN * HH) / 256, 256>>>();                                  // 0
    k_packall<<<1792, 256>>>(We1, We2, Wn1, Wn2, Wc1, Wf2);              // 1
    k_pre<<<dim3(nblk, 4), 256>>>(h);                                    // 2
    k_edge<<<EE / 32, 256, SME_BYTES>>>(pos, ei, ea, We1, be1, ge, beln, // 3
                                        be2, bc1, Wc2, Wa, ba);
    k_pos<<<(NN * 3 + 255) / 256, 256>>>(pos, outp);
    k_node1<<<nblk, 256, 32 * H2 * 4>>>(h, bn1, gn, bnln);
    k_node2<<<nblk, 256, 32 * H2 * 4>>>(h, bn2, go, boln, outh);
    k_fb<<<EE / 32, 256>>>(ei, outp, Wf1, bf1);
    k_fb2<<<nblk, 256>>>(bf2, outh);
}